// round 10
// baseline (speedup 1.0000x reference)
#include <cuda_runtime.h>
#include <math.h>

// ---------------------------------------------------------------------------
// FraudDetectionNet fused kernel.
//
// Per patch p: qcontrib_p = t01^T C_p t23 with b_q=(1,cos p_q,sin p_q),
// t01=b0(x)b1, t23=b2(x)b3, and C_p[s] = sum_m c_p[m] K[m][s].
// K collapsed to 16 XOR/sign terms per element:
//   K[m][s] = (1/16) sum_{n} (-1)^{popc(n&neg)}
//             (Ur[m,n]Ur[m,n^mask] + Ui[m,n]Ui[m,n^mask]),
//   mask_q=(s_q==2), neg_q=(s_q==1).
// c_p[m] folds Z and the classifier weights.
// C stored flat: 81 floats per patch padded to 84 (21 float4).
//
// mainK: smem holds ONLY C (66KB) -> 2 blocks/SM, 64 warps. Pixels are read
// straight from global (lane = image, block working set 100KB = L2-resident),
// with a one-patch software-pipeline prefetch.
// ---------------------------------------------------------------------------

#define NPATCH   196
#define CPP      84          // 81 used + 3 pad -> 21 float4 per patch
#define NIMG     32
#define NTHREADS 1024
#define NWARPS   32
#define SMEM_BYTES (NPATCH * CPP * 4)

__device__ float g_C[NPATCH * CPP];

// ---- fused precompute: K (collapsed form) + per-patch C -------------------
__global__ void kernelPre(const float* __restrict__ Ure,
                          const float* __restrict__ Uim,
                          const float* __restrict__ w_cls) {
    __shared__ float ur[256], ui[256];
    __shared__ float Ks[16 * 81];
    __shared__ float c[4][16];
    const int t = threadIdx.x;
    const int pbase = blockIdx.x * 4;

    ur[t] = Ure[t];
    ui[t] = Uim[t];
    if (t < 64) {
        int pp = t >> 4, m = t & 15;
        const float* wp = w_cls + 1 + 4 * (pbase + pp);
        float acc = 0.f;
#pragma unroll
        for (int w = 0; w < 4; ++w)
            acc = fmaf(1.f - 2.f * (float)((m >> (3 - w)) & 1), wp[w], acc);
        c[pp][m] = acc;
    }
    __syncthreads();

    for (int e = t; e < 16 * 81; e += 256) {
        int m = e / 81, s = e - m * 81;
        int s3 = s % 3, r = s / 3;
        int s2 = r % 3; r /= 3;
        int s1 = r % 3, s0 = r / 3;
        int mask = ((int)(s0 == 2) << 3) | ((int)(s1 == 2) << 2)
                 | ((int)(s2 == 2) << 1) | (int)(s3 == 2);
        int neg  = ((int)(s0 == 1) << 3) | ((int)(s1 == 1) << 2)
                 | ((int)(s2 == 1) << 1) | (int)(s3 == 1);
        const float* urm = ur + m * 16;
        const float* uim = ui + m * 16;
        float acc = 0.f;
#pragma unroll
        for (int n = 0; n < 16; ++n) {
            float v = urm[n] * urm[n ^ mask] + uim[n] * uim[n ^ mask];
            acc += (__popc(n & neg) & 1) ? -v : v;
        }
        Ks[e] = acc * 0.0625f;
    }
    __syncthreads();

    for (int e = t; e < 4 * CPP; e += 256) {
        int pp = e / CPP, k = e - pp * CPP;
        float v = 0.f;
        if (k < 81) {
#pragma unroll
            for (int m = 0; m < 16; ++m) v = fmaf(c[pp][m], Ks[m * 81 + k], v);
        }
        g_C[(pbase + pp) * CPP + k] = v;
    }
}

// ---- main fused kernel: 32 images per block, 32 warps, C-only smem --------
__global__ void __launch_bounds__(NTHREADS, 2)
mainK(const float* __restrict__ x,
      const float* __restrict__ w_in,   const float* __restrict__ b_in,
      const float* __restrict__ scale_in, const float* __restrict__ shift_in,
      const float* __restrict__ Wc,     const float* __restrict__ bc,
      const float* __restrict__ scalec, const float* __restrict__ shiftc,
      const float* __restrict__ w_out,  const float* __restrict__ b_out,
      const float* __restrict__ w_cls,  const float* __restrict__ b_cls,
      float* __restrict__ out, int B, int L)
{
    extern __shared__ float Cs[];         // NPATCH*CPP floats
    __shared__ float rq[NWARPS][33], ra[NWARPS][33], rb[NWARPS][33];

    const int tid  = threadIdx.x;
    const int w    = tid >> 5;
    const int lane = tid & 31;
    const int img_base = blockIdx.x * NIMG;
    int nimg = B - img_base;
    if (nimg > NIMG) nimg = NIMG;

    // stage C (float4, CPP divisible by 4)
    {
        const float4* gc4 = (const float4*)g_C;
        float4* cs4 = (float4*)Cs;
        for (int i = tid; i < NPATCH * CPP / 4; i += NTHREADS) cs4[i] = gc4[i];
    }
    __syncthreads();

    float qsum = 0.f, s1 = 0.f, s2 = 0.f;
    if (lane < nimg) {
        const float* xi = x + (size_t)(img_base + lane) * 784;
        const int pstart = (w * NPATCH) / NWARPS;
        const int pend   = ((w + 1) * NPATCH) / NWARPS;
        int pr = pstart / 14, pc = pstart - pr * 14;
        int off = pr * 56 + pc * 2;

        // software pipeline: prefetch first patch
        float2 tp = *(const float2*)(xi + off);
        float2 bt = *(const float2*)(xi + off + 28);

        for (int p = pstart; p < pend; ++p) {
            float2 ctp = tp, cbt = bt;
            // advance to next patch offset and prefetch
            if (++pc == 14) { pc = 0; off += 30; } else { off += 2; }
            if (p + 1 < pend) {
                tp = *(const float2*)(xi + off);
                bt = *(const float2*)(xi + off + 28);
            }

            s1 += (ctp.x + ctp.y) + (cbt.x + cbt.y);
            s2 = fmaf(ctp.x, ctp.x, fmaf(ctp.y, ctp.y,
                 fmaf(cbt.x, cbt.x, fmaf(cbt.y, cbt.y, s2))));

            float c0v, s0v, c1v, s1v, c2v, s2v, c3v, s3v;
            __sincosf(ctp.x, &s0v, &c0v);
            __sincosf(ctp.y, &s1v, &c1v);
            __sincosf(cbt.x, &s2v, &c2v);
            __sincosf(cbt.y, &s3v, &c3v);

            // t23 = [1, c3, s3, c2, c2c3, c2s3, s2, s2c3, s2s3]
            float t23a[9];
            t23a[0] = 1.f;
            t23a[1] = c3v;        t23a[2] = s3v;
            t23a[3] = c2v;        t23a[4] = c2v * c3v;
            t23a[5] = c2v * s3v;  t23a[6] = s2v;
            t23a[7] = s2v * c3v;  t23a[8] = s2v * s3v;

            const float4* Cp4 = (const float4*)(Cs + p * CPP);
            float d[9];
#pragma unroll
            for (int q = 0; q < 21; ++q) {
                float4 f = Cp4[q];
#pragma unroll
                for (int u = 0; u < 4; ++u) {
                    int k = 4 * q + u;
                    if (k >= 81) break;
                    float v = (u == 0) ? f.x : (u == 1) ? f.y : (u == 2) ? f.z : f.w;
                    int i = k / 9, j = k - 9 * i;
                    if (j == 0) d[i] = v;
                    else        d[i] = fmaf(v, t23a[j], d[i]);
                }
            }
            // acc = sum_i t01[i] d[i], t01 = (1,c0,s0)(x)(1,c1,s1) nested:
            float e0 = fmaf(d[2], s1v, fmaf(d[1], c1v, d[0]));
            float e1 = fmaf(d[5], s1v, fmaf(d[4], c1v, d[3]));
            float e2 = fmaf(d[8], s1v, fmaf(d[7], c1v, d[6]));
            qsum = fmaf(e2, s0v, fmaf(e1, c0v, e0 + qsum));
        }
    }

    rq[w][lane] = qsum; ra[w][lane] = s1; rb[w][lane] = s2;
    __syncthreads();

    if (tid < 32 && tid < nimg) {
        float Q = 0.f, S1 = 0.f, S2 = 0.f;
#pragma unroll
        for (int k = 0; k < NWARPS; ++k) { Q += rq[k][tid]; S1 += ra[k][tid]; S2 += rb[k][tid]; }
        float mean = S1 * (1.f / 784.f);
        float var  = (S2 - S1 * S1 * (1.f / 784.f)) * (1.f / 783.f);
        float stdv = sqrtf(fmaxf(var, 0.f));
        float h0 = tanhf(fmaf(mean, w_in[0], fmaf(stdv, w_in[1], b_in[0]))) * scale_in[0] + shift_in[0];
        float h1 = tanhf(fmaf(mean, w_in[2], fmaf(stdv, w_in[3], b_in[1]))) * scale_in[1] + shift_in[1];
        for (int i = 0; i < L; ++i) {
            float n0 = tanhf(fmaf(h0, Wc[i*4+0], fmaf(h1, Wc[i*4+1], bc[i*2+0]))) * scalec[i*2+0] + shiftc[i*2+0];
            float n1 = tanhf(fmaf(h0, Wc[i*4+2], fmaf(h1, Wc[i*4+3], bc[i*2+1]))) * scalec[i*2+1] + shiftc[i*2+1];
            h0 = n0; h1 = n1;
        }
        float cls   = fmaf(h0, w_out[0], fmaf(h1, w_out[1], b_out[0]));
        float logit = fmaf(cls, w_cls[0], Q + b_cls[0]);
        out[img_base + tid] = 1.f / (1.f + expf(-logit));
    }
}

extern "C" void kernel_launch(void* const* d_in, const int* in_sizes, int n_in,
                              void* d_out, int out_size) {
    const float* x        = (const float*)d_in[0];
    const float* w_in     = (const float*)d_in[1];
    const float* b_in     = (const float*)d_in[2];
    const float* scale_in = (const float*)d_in[3];
    const float* shift_in = (const float*)d_in[4];
    const float* Wc       = (const float*)d_in[5];
    const float* bc       = (const float*)d_in[6];
    const float* scalec   = (const float*)d_in[7];
    const float* shiftc   = (const float*)d_in[8];
    const float* w_out    = (const float*)d_in[9];
    const float* b_out    = (const float*)d_in[10];
    const float* U_re     = (const float*)d_in[11];
    const float* U_im     = (const float*)d_in[12];
    const float* w_cls    = (const float*)d_in[13];
    const float* b_cls    = (const float*)d_in[14];
    float* out = (float*)d_out;

    int B = in_sizes[0] / 784;
    int L = in_sizes[5] / 4;

    cudaFuncSetAttribute(mainK, cudaFuncAttributeMaxDynamicSharedMemorySize, SMEM_BYTES);

    kernelPre<<<NPATCH / 4, 256>>>(U_re, U_im, w_cls);
    mainK<<<(B + NIMG - 1) / NIMG, NTHREADS, SMEM_BYTES>>>(
        x, w_in, b_in, scale_in, shift_in, Wc, bc, scalec, shiftc,
        w_out, b_out, w_cls, b_cls, out, B, L);
}

// round 11
// speedup vs baseline: 1.5829x; 1.5829x over previous
#include <cuda_runtime.h>
#include <math.h>

// ---------------------------------------------------------------------------
// FraudDetectionNet fused kernel.
//
// Per patch p: qcontrib_p = t01^T C_p t23 with b_q=(1,cos p_q,sin p_q).
// C_p[s] = sum_m c_p[m] K[m][s];  K collapsed to 16 XOR/sign terms:
//   K[m][s] = (1/16) sum_n (-1)^{popc(n&neg)}
//             (Ur[m,n]Ur[m,n^mask] + Ui[m,n]Ui[m,n^mask]),
//   mask_q=(s_q==2), neg_q=(s_q==1).  c_p[m] folds Z + classifier weights.
// C flat: 81 floats/patch padded to 84 (21 float4), pad = 0.
//
// mainK: 512 threads, 64 images/block (2 per thread: lane and lane+32),
// single wave (128 blocks). C in smem (66KB, warp-uniform broadcast reads),
// each C float4 feeds BOTH images -> 18 independent FMA chains (ILP).
// Pixels read from global (L2-resident). Full 128-reg budget, no spills.
// ---------------------------------------------------------------------------

#define NPATCH   196
#define CPP      84          // 81 used + 3 zero-pad -> 21 float4 per patch
#define NIMG     64
#define NTHREADS 512
#define NWARPS   16
#define SMEM_BYTES (NPATCH * CPP * 4)

__device__ float g_C[NPATCH * CPP];

// ---- fused precompute: K (collapsed form) + per-patch C -------------------
__global__ void kernelPre(const float* __restrict__ Ure,
                          const float* __restrict__ Uim,
                          const float* __restrict__ w_cls) {
    __shared__ float ur[256], ui[256];
    __shared__ float Ks[16 * 81];
    __shared__ float c[4][16];
    const int t = threadIdx.x;
    const int pbase = blockIdx.x * 4;

    ur[t] = Ure[t];
    ui[t] = Uim[t];
    if (t < 64) {
        int pp = t >> 4, m = t & 15;
        const float* wp = w_cls + 1 + 4 * (pbase + pp);
        float acc = 0.f;
#pragma unroll
        for (int w = 0; w < 4; ++w)
            acc = fmaf(1.f - 2.f * (float)((m >> (3 - w)) & 1), wp[w], acc);
        c[pp][m] = acc;
    }
    __syncthreads();

    for (int e = t; e < 16 * 81; e += 256) {
        int m = e / 81, s = e - m * 81;
        int s3 = s % 3, r = s / 3;
        int s2 = r % 3; r /= 3;
        int s1 = r % 3, s0 = r / 3;
        int mask = ((int)(s0 == 2) << 3) | ((int)(s1 == 2) << 2)
                 | ((int)(s2 == 2) << 1) | (int)(s3 == 2);
        int neg  = ((int)(s0 == 1) << 3) | ((int)(s1 == 1) << 2)
                 | ((int)(s2 == 1) << 1) | (int)(s3 == 1);
        const float* urm = ur + m * 16;
        const float* uim = ui + m * 16;
        float acc = 0.f;
#pragma unroll
        for (int n = 0; n < 16; ++n) {
            float v = urm[n] * urm[n ^ mask] + uim[n] * uim[n ^ mask];
            acc += (__popc(n & neg) & 1) ? -v : v;
        }
        Ks[e] = acc * 0.0625f;
    }
    __syncthreads();

    for (int e = t; e < 4 * CPP; e += 256) {
        int pp = e / CPP, k = e - pp * CPP;
        float v = 0.f;
        if (k < 81) {
#pragma unroll
            for (int m = 0; m < 16; ++m) v = fmaf(c[pp][m], Ks[m * 81 + k], v);
        }
        g_C[(pbase + pp) * CPP + k] = v;
    }
}

// ---- main fused kernel: 64 images per block, 2 per thread -----------------
__global__ void __launch_bounds__(NTHREADS, 1)
mainK(const float* __restrict__ x,
      const float* __restrict__ w_in,   const float* __restrict__ b_in,
      const float* __restrict__ scale_in, const float* __restrict__ shift_in,
      const float* __restrict__ Wc,     const float* __restrict__ bc,
      const float* __restrict__ scalec, const float* __restrict__ shiftc,
      const float* __restrict__ w_out,  const float* __restrict__ b_out,
      const float* __restrict__ w_cls,  const float* __restrict__ b_cls,
      float* __restrict__ out, int B, int L)
{
    extern __shared__ float Cs[];         // NPATCH*CPP floats
    __shared__ float rq[NWARPS][NIMG], rs1[NWARPS][NIMG], rs2[NWARPS][NIMG];

    const int tid  = threadIdx.x;
    const int w    = tid >> 5;
    const int lane = tid & 31;
    const int img_base = blockIdx.x * NIMG;
    int nimg = B - img_base;
    if (nimg > NIMG) nimg = NIMG;

    // stage C (float4, CPP divisible by 4)
    {
        const float4* gc4 = (const float4*)g_C;
        float4* cs4 = (float4*)Cs;
        for (int i = tid; i < NPATCH * CPP / 4; i += NTHREADS) cs4[i] = gc4[i];
    }
    __syncthreads();

    const bool hasA = lane < nimg;
    const bool hasB = (lane + 32) < nimg;
    const float* xiA = x + (size_t)(img_base + lane) * 784;
    const float* xiB = x + (size_t)(img_base + lane + 32) * 784;
    if (!hasA) xiA = x;            // safe dummy
    if (!hasB) xiB = x;

    float qA = 0.f, s1A = 0.f, s2A = 0.f;
    float qB = 0.f, s1B = 0.f, s2B = 0.f;

    {
        const int pstart = (w * NPATCH) / NWARPS;
        const int pend   = ((w + 1) * NPATCH) / NWARPS;
        int pr = pstart / 14, pc = pstart - pr * 14;
        int off = pr * 56 + pc * 2;

        // software pipeline: prefetch first patch for both images
        float2 tpA = *(const float2*)(xiA + off);
        float2 btA = *(const float2*)(xiA + off + 28);
        float2 tpB = *(const float2*)(xiB + off);
        float2 btB = *(const float2*)(xiB + off + 28);

        for (int p = pstart; p < pend; ++p) {
            float2 cA0 = tpA, cA1 = btA, cB0 = tpB, cB1 = btB;
            if (++pc == 14) { pc = 0; off += 30; } else { off += 2; }
            if (p + 1 < pend) {
                tpA = *(const float2*)(xiA + off);
                btA = *(const float2*)(xiA + off + 28);
                tpB = *(const float2*)(xiB + off);
                btB = *(const float2*)(xiB + off + 28);
            }

            s1A += (cA0.x + cA0.y) + (cA1.x + cA1.y);
            s2A = fmaf(cA0.x, cA0.x, fmaf(cA0.y, cA0.y,
                  fmaf(cA1.x, cA1.x, fmaf(cA1.y, cA1.y, s2A))));
            s1B += (cB0.x + cB0.y) + (cB1.x + cB1.y);
            s2B = fmaf(cB0.x, cB0.x, fmaf(cB0.y, cB0.y,
                  fmaf(cB1.x, cB1.x, fmaf(cB1.y, cB1.y, s2B))));

            float ta[9], tb[9];
            float a0c, a0s, a1c, a1s, a2c, a2s, a3c, a3s;
            __sincosf(cA0.x, &a0s, &a0c);
            __sincosf(cA0.y, &a1s, &a1c);
            __sincosf(cA1.x, &a2s, &a2c);
            __sincosf(cA1.y, &a3s, &a3c);
            ta[0] = 1.f;
            ta[1] = a3c;        ta[2] = a3s;
            ta[3] = a2c;        ta[4] = a2c * a3c;
            ta[5] = a2c * a3s;  ta[6] = a2s;
            ta[7] = a2s * a3c;  ta[8] = a2s * a3s;
            float A0c = a0c, A0s = a0s, A1c = a1c, A1s = a1s;

            float b0c, b0s, b1c, b1s, b2c, b2s, b3c, b3s;
            __sincosf(cB0.x, &b0s, &b0c);
            __sincosf(cB0.y, &b1s, &b1c);
            __sincosf(cB1.x, &b2s, &b2c);
            __sincosf(cB1.y, &b3s, &b3c);
            tb[0] = 1.f;
            tb[1] = b3c;        tb[2] = b3s;
            tb[3] = b2c;        tb[4] = b2c * b3c;
            tb[5] = b2c * b3s;  tb[6] = b2s;
            tb[7] = b2s * b3c;  tb[8] = b2s * b3s;

            const float4* Cp4 = (const float4*)(Cs + p * CPP);
            float dA[9], dB[9];
#pragma unroll
            for (int q = 0; q < 21; ++q) {
                float4 f = Cp4[q];
#pragma unroll
                for (int u = 0; u < 4; ++u) {
                    int k = 4 * q + u;
                    if (k >= 81) break;
                    float v = (u == 0) ? f.x : (u == 1) ? f.y : (u == 2) ? f.z : f.w;
                    int i = k / 9, j = k - 9 * i;
                    if (j == 0) { dA[i] = v;            dB[i] = v; }
                    else        { dA[i] = fmaf(v, ta[j], dA[i]);
                                  dB[i] = fmaf(v, tb[j], dB[i]); }
                }
            }
            float eA0 = fmaf(dA[2], A1s, fmaf(dA[1], A1c, dA[0]));
            float eA1 = fmaf(dA[5], A1s, fmaf(dA[4], A1c, dA[3]));
            float eA2 = fmaf(dA[8], A1s, fmaf(dA[7], A1c, dA[6]));
            qA = fmaf(eA2, A0s, fmaf(eA1, A0c, eA0 + qA));
            float eB0 = fmaf(dB[2], b1s, fmaf(dB[1], b1c, dB[0]));
            float eB1 = fmaf(dB[5], b1s, fmaf(dB[4], b1c, dB[3]));
            float eB2 = fmaf(dB[8], b1s, fmaf(dB[7], b1c, dB[6]));
            qB = fmaf(eB2, b0s, fmaf(eB1, b0c, eB0 + qB));
        }
    }

    rq[w][lane]      = qA;  rs1[w][lane]      = s1A;  rs2[w][lane]      = s2A;
    rq[w][lane + 32] = qB;  rs1[w][lane + 32] = s1B;  rs2[w][lane + 32] = s2B;
    __syncthreads();

    if (tid < NIMG && tid < nimg) {
        float Q = 0.f, S1 = 0.f, S2 = 0.f;
#pragma unroll
        for (int k = 0; k < NWARPS; ++k) {
            Q += rq[k][tid]; S1 += rs1[k][tid]; S2 += rs2[k][tid];
        }
        float mean = S1 * (1.f / 784.f);
        float var  = (S2 - S1 * S1 * (1.f / 784.f)) * (1.f / 783.f);
        float stdv = sqrtf(fmaxf(var, 0.f));
        float h0 = tanhf(fmaf(mean, w_in[0], fmaf(stdv, w_in[1], b_in[0]))) * scale_in[0] + shift_in[0];
        float h1 = tanhf(fmaf(mean, w_in[2], fmaf(stdv, w_in[3], b_in[1]))) * scale_in[1] + shift_in[1];
        for (int i = 0; i < L; ++i) {
            float n0 = tanhf(fmaf(h0, Wc[i*4+0], fmaf(h1, Wc[i*4+1], bc[i*2+0]))) * scalec[i*2+0] + shiftc[i*2+0];
            float n1 = tanhf(fmaf(h0, Wc[i*4+2], fmaf(h1, Wc[i*4+3], bc[i*2+1]))) * scalec[i*2+1] + shiftc[i*2+1];
            h0 = n0; h1 = n1;
        }
        float cls   = fmaf(h0, w_out[0], fmaf(h1, w_out[1], b_out[0]));
        float logit = fmaf(cls, w_cls[0], Q + b_cls[0]);
        out[img_base + tid] = 1.f / (1.f + expf(-logit));
    }
}

extern "C" void kernel_launch(void* const* d_in, const int* in_sizes, int n_in,
                              void* d_out, int out_size) {
    const float* x        = (const float*)d_in[0];
    const float* w_in     = (const float*)d_in[1];
    const float* b_in     = (const float*)d_in[2];
    const float* scale_in = (const float*)d_in[3];
    const float* shift_in = (const float*)d_in[4];
    const float* Wc       = (const float*)d_in[5];
    const float* bc       = (const float*)d_in[6];
    const float* scalec   = (const float*)d_in[7];
    const float* shiftc   = (const float*)d_in[8];
    const float* w_out    = (const float*)d_in[9];
    const float* b_out    = (const float*)d_in[10];
    const float* U_re     = (const float*)d_in[11];
    const float* U_im     = (const float*)d_in[12];
    const float* w_cls    = (const float*)d_in[13];
    const float* b_cls    = (const float*)d_in[14];
    float* out = (float*)d_out;

    int B = in_sizes[0] / 784;
    int L = in_sizes[5] / 4;

    cudaFuncSetAttribute(mainK, cudaFuncAttributeMaxDynamicSharedMemorySize, SMEM_BYTES);

    kernelPre<<<NPATCH / 4, 256>>>(U_re, U_im, w_cls);
    mainK<<<(B + NIMG - 1) / NIMG, NTHREADS, SMEM_BYTES>>>(
        x, w_in, b_in, scale_in, shift_in, Wc, bc, scalec, shiftc,
        w_out, b_out, w_cls, b_cls, out, B, L);
}

// round 13
// speedup vs baseline: 1.6624x; 1.0502x over previous
#include <cuda_runtime.h>
#include <math.h>

// ---------------------------------------------------------------------------
// FraudDetectionNet fused kernel.
//
// Per patch p: qcontrib_p = t01^T C_p t23 with b_q=(1,cos p_q,sin p_q).
// C_p[s] = sum_m c_p[m] K[m][s];  K collapsed to 16 XOR/sign terms:
//   K[m][s] = (1/16) sum_n (-1)^{popc(n&neg)}
//             (Ur[m,n]Ur[m,n^mask] + Ui[m,n]Ui[m,n^mask]),
//   mask_q=(s_q==2), neg_q=(s_q==1).  c_p[m] folds Z + classifier weights.
// C flat: 81 floats/patch padded to 84 (21 float4), pad = 0.
//
// mainK: 512 threads, 64 images/block (2 per thread), single wave (128
// blocks). C in smem (66KB). Images staged in smem in TWO half-image phases
// (100.9KB buffer, stride 394 floats -> conflict-free LDS.64), so hot-loop
// pixel reads are smem broadcasts instead of 32-way-scattered LDG.
// Stats (mean/std) folded into the coalesced staging pass.
// ---------------------------------------------------------------------------

#define NPATCH   196
#define CPP      84          // 81 used + 3 zero-pad -> 21 float4 per patch
#define NIMG     64
#define NTHREADS 512
#define NWARPS   16
#define XS2      394         // half-image stride: 392 + 2 (197 odd -> no conflicts)
#define SMEM_BYTES ((NPATCH*CPP + NIMG*XS2) * 4)

__device__ float g_C[NPATCH * CPP];

// ---- fused precompute: K (collapsed form) + per-patch C -------------------
__global__ void kernelPre(const float* __restrict__ Ure,
                          const float* __restrict__ Uim,
                          const float* __restrict__ w_cls) {
    __shared__ float ur[256], ui[256];
    __shared__ float Ks[16 * 81];
    __shared__ float c[4][16];
    const int t = threadIdx.x;
    const int pbase = blockIdx.x * 4;

    ur[t] = Ure[t];
    ui[t] = Uim[t];
    if (t < 64) {
        int pp = t >> 4, m = t & 15;
        const float* wp = w_cls + 1 + 4 * (pbase + pp);
        float acc = 0.f;
#pragma unroll
        for (int w = 0; w < 4; ++w)
            acc = fmaf(1.f - 2.f * (float)((m >> (3 - w)) & 1), wp[w], acc);
        c[pp][m] = acc;
    }
    __syncthreads();

    for (int e = t; e < 16 * 81; e += 256) {
        int m = e / 81, s = e - m * 81;
        int s3 = s % 3, r = s / 3;
        int s2 = r % 3; r /= 3;
        int s1 = r % 3, s0 = r / 3;
        int mask = ((int)(s0 == 2) << 3) | ((int)(s1 == 2) << 2)
                 | ((int)(s2 == 2) << 1) | (int)(s3 == 2);
        int neg  = ((int)(s0 == 1) << 3) | ((int)(s1 == 1) << 2)
                 | ((int)(s2 == 1) << 1) | (int)(s3 == 1);
        const float* urm = ur + m * 16;
        const float* uim = ui + m * 16;
        float acc = 0.f;
#pragma unroll
        for (int n = 0; n < 16; ++n) {
            float v = urm[n] * urm[n ^ mask] + uim[n] * uim[n ^ mask];
            acc += (__popc(n & neg) & 1) ? -v : v;
        }
        Ks[e] = acc * 0.0625f;
    }
    __syncthreads();

    for (int e = t; e < 4 * CPP; e += 256) {
        int pp = e / CPP, k = e - pp * CPP;
        float v = 0.f;
        if (k < 81) {
#pragma unroll
            for (int m = 0; m < 16; ++m) v = fmaf(c[pp][m], Ks[m * 81 + k], v);
        }
        g_C[(pbase + pp) * CPP + k] = v;
    }
}

// ---- main fused kernel: 64 images/block, 2 per thread, 2 half-img phases --
__global__ void __launch_bounds__(NTHREADS, 1)
mainK(const float* __restrict__ x,
      const float* __restrict__ w_in,   const float* __restrict__ b_in,
      const float* __restrict__ scale_in, const float* __restrict__ shift_in,
      const float* __restrict__ Wc,     const float* __restrict__ bc,
      const float* __restrict__ scalec, const float* __restrict__ shiftc,
      const float* __restrict__ w_out,  const float* __restrict__ b_out,
      const float* __restrict__ w_cls,  const float* __restrict__ b_cls,
      float* __restrict__ out, int B, int L)
{
    extern __shared__ float sm[];
    float* Cs = sm;                       // NPATCH*CPP floats
    float* xs = sm + NPATCH * CPP;        // NIMG*XS2 floats (half images)
    __shared__ float rq[NWARPS][NIMG];
    __shared__ float sS1[NIMG], sS2[NIMG];

    const int tid  = threadIdx.x;
    const int w    = tid >> 5;
    const int lane = tid & 31;
    const int img_base = blockIdx.x * NIMG;
    int nimg = B - img_base;
    if (nimg > NIMG) nimg = NIMG;

    // stage C (float4, CPP divisible by 4)
    {
        const float4* gc4 = (const float4*)g_C;
        float4* cs4 = (float4*)Cs;
        for (int i = tid; i < NPATCH * CPP / 4; i += NTHREADS) cs4[i] = gc4[i];
    }

    const bool hasA = lane < nimg;
    const bool hasB = (lane + 32) < nimg;
    const float* xsA = xs + lane * XS2;
    const float* xsB = xs + (lane + 32) * XS2;

    float qA = 0.f, qB = 0.f;
    float ls1[4] = {0.f, 0.f, 0.f, 0.f};
    float ls2[4] = {0.f, 0.f, 0.f, 0.f};

    const int pstartL = (w * 98) / NWARPS;        // local patch range per phase
    const int pendL   = ((w + 1) * 98) / NWARPS;

    for (int h = 0; h < 2; ++h) {
        if (h) __syncthreads();                   // phase-0 compute done

        // stage half-image h for images w, w+16, w+32, w+48 (coalesced) + stats
#pragma unroll
        for (int j = 0; j < 4; ++j) {
            int img = w + 16 * j;
            if (img < nimg) {
                const float4* src = (const float4*)(x + (size_t)(img_base + img) * 784)
                                    + 98 * h;
                float* dst = xs + img * XS2;
                for (int k = lane; k < 98; k += 32) {
                    float4 v = src[k];
                    dst[4 * k + 0] = v.x; dst[4 * k + 1] = v.y;
                    dst[4 * k + 2] = v.z; dst[4 * k + 3] = v.w;
                    ls1[j] += (v.x + v.y) + (v.z + v.w);
                    ls2[j] = fmaf(v.x, v.x, fmaf(v.y, v.y,
                             fmaf(v.z, v.z, fmaf(v.w, v.w, ls2[j]))));
                }
            }
        }
        __syncthreads();

        // compute local patches [pstartL, pendL) of this half
        int pr = pstartL / 14, pc = pstartL - pr * 14;
        int loff = pr * 56 + pc * 2;

        float2 tpA = *(const float2*)(xsA + loff);
        float2 btA = *(const float2*)(xsA + loff + 28);
        float2 tpB = *(const float2*)(xsB + loff);
        float2 btB = *(const float2*)(xsB + loff + 28);

        const int pgbase = 98 * h;
        for (int p = pstartL; p < pendL; ++p) {
            float2 cA0 = tpA, cA1 = btA, cB0 = tpB, cB1 = btB;
            if (++pc == 14) { pc = 0; loff += 30; } else { loff += 2; }
            if (p + 1 < pendL) {
                tpA = *(const float2*)(xsA + loff);
                btA = *(const float2*)(xsA + loff + 28);
                tpB = *(const float2*)(xsB + loff);
                btB = *(const float2*)(xsB + loff + 28);
            }

            float ta[9], tb[9];
            float a0c, a0s, a1c, a1s, a2c, a2s, a3c, a3s;
            __sincosf(cA0.x, &a0s, &a0c);
            __sincosf(cA0.y, &a1s, &a1c);
            __sincosf(cA1.x, &a2s, &a2c);
            __sincosf(cA1.y, &a3s, &a3c);
            ta[0] = 1.f;
            ta[1] = a3c;        ta[2] = a3s;
            ta[3] = a2c;        ta[4] = a2c * a3c;
            ta[5] = a2c * a3s;  ta[6] = a2s;
            ta[7] = a2s * a3c;  ta[8] = a2s * a3s;

            float b0c, b0s, b1c, b1s, b2c, b2s, b3c, b3s;
            __sincosf(cB0.x, &b0s, &b0c);
            __sincosf(cB0.y, &b1s, &b1c);
            __sincosf(cB1.x, &b2s, &b2c);
            __sincosf(cB1.y, &b3s, &b3c);
            tb[0] = 1.f;
            tb[1] = b3c;        tb[2] = b3s;
            tb[3] = b2c;        tb[4] = b2c * b3c;
            tb[5] = b2c * b3s;  tb[6] = b2s;
            tb[7] = b2s * b3c;  tb[8] = b2s * b3s;

            const float4* Cp4 = (const float4*)(Cs + (pgbase + p) * CPP);
            float dA[9], dB[9];
#pragma unroll
            for (int q = 0; q < 21; ++q) {
                float4 f = Cp4[q];
#pragma unroll
                for (int u = 0; u < 4; ++u) {
                    int k = 4 * q + u;
                    if (k >= 81) break;
                    float v = (u == 0) ? f.x : (u == 1) ? f.y : (u == 2) ? f.z : f.w;
                    int i = k / 9, j = k - 9 * i;
                    if (j == 0) { dA[i] = v;            dB[i] = v; }
                    else        { dA[i] = fmaf(v, ta[j], dA[i]);
                                  dB[i] = fmaf(v, tb[j], dB[i]); }
                }
            }
            float eA0 = fmaf(dA[2], a1s, fmaf(dA[1], a1c, dA[0]));
            float eA1 = fmaf(dA[5], a1s, fmaf(dA[4], a1c, dA[3]));
            float eA2 = fmaf(dA[8], a1s, fmaf(dA[7], a1c, dA[6]));
            qA = fmaf(eA2, a0s, fmaf(eA1, a0c, eA0 + qA));
            float eB0 = fmaf(dB[2], b1s, fmaf(dB[1], b1c, dB[0]));
            float eB1 = fmaf(dB[5], b1s, fmaf(dB[4], b1c, dB[3]));
            float eB2 = fmaf(dB[8], b1s, fmaf(dB[7], b1c, dB[6]));
            qB = fmaf(eB2, b0s, fmaf(eB1, b0c, eB0 + qB));
        }
    }

    // stats: shuffle-reduce the 4 staged images per warp
#pragma unroll
    for (int j = 0; j < 4; ++j) {
        float a = ls1[j], b = ls2[j];
#pragma unroll
        for (int o = 16; o > 0; o >>= 1) {
            a += __shfl_down_sync(0xffffffffu, a, o);
            b += __shfl_down_sync(0xffffffffu, b, o);
        }
        if (lane == 0) { sS1[w + 16 * j] = a; sS2[w + 16 * j] = b; }
    }
    rq[w][lane]      = hasA ? qA : 0.f;
    rq[w][lane + 32] = hasB ? qB : 0.f;
    __syncthreads();

    if (tid < NIMG && tid < nimg) {
        float Q = 0.f;
#pragma unroll
        for (int k = 0; k < NWARPS; ++k) Q += rq[k][tid];
        float S1 = sS1[tid], S2 = sS2[tid];
        float mean = S1 * (1.f / 784.f);
        float var  = (S2 - S1 * S1 * (1.f / 784.f)) * (1.f / 783.f);
        float stdv = sqrtf(fmaxf(var, 0.f));
        float h0 = tanhf(fmaf(mean, w_in[0], fmaf(stdv, w_in[1], b_in[0]))) * scale_in[0] + shift_in[0];
        float h1 = tanhf(fmaf(mean, w_in[2], fmaf(stdv, w_in[3], b_in[1]))) * scale_in[1] + shift_in[1];
        for (int i = 0; i < L; ++i) {
            float n0 = tanhf(fmaf(h0, Wc[i*4+0], fmaf(h1, Wc[i*4+1], bc[i*2+0]))) * scalec[i*2+0] + shiftc[i*2+0];
            float n1 = tanhf(fmaf(h0, Wc[i*4+2], fmaf(h1, Wc[i*4+3], bc[i*2+1]))) * scalec[i*2+1] + shiftc[i*2+1];
            h0 = n0; h1 = n1;
        }
        float cls   = fmaf(h0, w_out[0], fmaf(h1, w_out[1], b_out[0]));
        float logit = fmaf(cls, w_cls[0], Q + b_cls[0]);
        out[img_base + tid] = 1.f / (1.f + expf(-logit));
    }
}

extern "C" void kernel_launch(void* const* d_in, const int* in_sizes, int n_in,
                              void* d_out, int out_size) {
    const float* x        = (const float*)d_in[0];
    const float* w_in     = (const float*)d_in[1];
    const float* b_in     = (const float*)d_in[2];
    const float* scale_in = (const float*)d_in[3];
    const float* shift_in = (const float*)d_in[4];
    const float* Wc       = (const float*)d_in[5];
    const float* bc       = (const float*)d_in[6];
    const float* scalec   = (const float*)d_in[7];
    const float* shiftc   = (const float*)d_in[8];
    const float* w_out    = (const float*)d_in[9];
    const float* b_out    = (const float*)d_in[10];
    const float* U_re     = (const float*)d_in[11];
    const float* U_im     = (const float*)d_in[12];
    const float* w_cls    = (const float*)d_in[13];
    const float* b_cls    = (const float*)d_in[14];
    float* out = (float*)d_out;

    int B = in_sizes[0] / 784;
    int L = in_sizes[5] / 4;

    cudaFuncSetAttribute(mainK, cudaFuncAttributeMaxDynamicSharedMemorySize, SMEM_BYTES);

    kernelPre<<<NPATCH / 4, 256>>>(U_re, U_im, w_cls);
    mainK<<<(B + NIMG - 1) / NIMG, NTHREADS, SMEM_BYTES>>>(
        x, w_in, b_in, scale_in, shift_in, Wc, bc, scalec, shiftc,
        w_out, b_out, w_cls, b_cls, out, B, L);
}